// round 12
// baseline (speedup 1.0000x reference)
#include <cuda_runtime.h>

// x: [8, 64, 64, 64, 64] fp32. Per (b,c) slice of 64^3:
//   s = sum over 2x2x2 windows of (max(window) + mean(window))
//   pooled[b,c] = s^2 ;  out[b,c] = pooled / max(||pooled[b,:]||_2, 1e-12)
//
// CONVERGED CONFIG (best of 10-round sweep): 2048 blocks x 128 threads =
// 512 slices x 4 quarter-slices (256 KB each). 32 regs -> all 2048 blocks
// resident in one wave (14/SM needed, 16 cap). Plain LDG.128, fully
// coalesced, 4 batched loads/iter. Fused last-block finalize (atomic
// ticket). Sweep evidence: DRAM% pinned at ~80-81% regardless of occupancy
// (42-85%), granularity (64-256 thr), or scheduling (static/balanced/
// stealing) -> this is the chip's streaming-read plateau; 512 MiB / 6.5 TB/s
// ~= 80 us is the floor.

#define CH 4
#define NBC 512
#define NBLK (NBC * CH)   // 2048

__device__ float g_partial[NBLK];
__device__ unsigned int g_counter = 0;

__global__ __launch_bounds__(128, 16) void fused_pool_kernel(const float* __restrict__ x,
                                                             float* __restrict__ out) {
    const int bc = blockIdx.x >> 2;
    const int q  = blockIdx.x & 3;     // quarter: h2 in [q*8, q*8+8)

    const int tid = threadIdx.x;       // 128 threads
    const int tx  = tid & 15;          // d-group: d = 4*tx..4*tx+3 (two d2 windows)
    const int g   = tid >> 4;          // 0..7: w2 start; strides w2 by 8

    // start: h2 = q*8, w2 = g, d = 4*tx
    const float* r0 = x + (size_t)bc * (64 * 64 * 64)
                        + ((size_t)(q * 16) * 4096) + (2 * g * 64) + (tx << 2);

    float acc = 0.0f;

    for (int h2i = 0; h2i < 8; h2i++) {           // 8 h2 rows in this quarter
        const float* r = r0;
        #pragma unroll
        for (int w2i = 0; w2i < 4; w2i++) {       // w2 = g, g+8, g+16, g+24
            const float4 a = *(const float4*)(r);                 // (2h2,   2w2  )
            const float4 b = *(const float4*)(r + 64);            // (2h2,   2w2+1)
            const float4 c = *(const float4*)(r + 4096);          // (2h2+1, 2w2  )
            const float4 d = *(const float4*)(r + 4096 + 64);     // (2h2+1, 2w2+1)

            float m0 = fmaxf(fmaxf(fmaxf(a.x, a.y), fmaxf(b.x, b.y)),
                             fmaxf(fmaxf(c.x, c.y), fmaxf(d.x, d.y)));
            float m1 = fmaxf(fmaxf(fmaxf(a.z, a.w), fmaxf(b.z, b.w)),
                             fmaxf(fmaxf(c.z, c.w), fmaxf(d.z, d.w)));

            float sum = (a.x + a.y + a.z + a.w) + (b.x + b.y + b.z + b.w)
                      + (c.x + c.y + c.z + c.w) + (d.x + d.y + d.z + d.w);

            acc += m0 + m1 + sum * 0.125f;
            r += 2 * 8 * 64;                      // w2 += 8
        }
        r0 += 2 * 4096;                           // h2 += 1
    }

    // block reduce: warp shuffle then smem across 4 warps
    __shared__ float swarp[4];
    __shared__ int s_islast;
    #pragma unroll
    for (int off = 16; off > 0; off >>= 1)
        acc += __shfl_xor_sync(0xFFFFFFFFu, acc, off);
    if ((tid & 31) == 0) swarp[tid >> 5] = acc;
    __syncthreads();

    if (tid == 0) {
        float t = swarp[0] + swarp[1] + swarp[2] + swarp[3];
        g_partial[blockIdx.x] = t;
        __threadfence();                          // publish before ticket
        unsigned int old = atomicAdd(&g_counter, 1u);
        s_islast = (old == (unsigned int)(gridDim.x - 1));
    }
    __syncthreads();
    if (!s_islast) return;

    // ---- last block: finalize (all 2048 partials visible) ----
    __threadfence();
    __shared__ float s_norm[8];

    // thread t -> batch b = t>>4, channels c4 = (t&15)*4 .. +3
    const int b  = tid >> 4;           // 0..7
    const int c4 = (tid & 15) << 2;    // 0,4,...,60

    float p[4], qsum = 0.0f;
    #pragma unroll
    for (int k = 0; k < 4; k++) {
        const int idx = ((b << 6) + c4 + k) * CH;
        const float s = g_partial[idx] + g_partial[idx + 1]
                      + g_partial[idx + 2] + g_partial[idx + 3];
        p[k] = s * s;
        qsum += p[k] * p[k];
    }

    // reduce qsum over the 16 threads of the same batch (contiguous lanes)
    #pragma unroll
    for (int off = 8; off > 0; off >>= 1)
        qsum += __shfl_xor_sync(0xFFFFFFFFu, qsum, off);

    if ((tid & 15) == 0) s_norm[b] = fmaxf(sqrtf(qsum), 1e-12f);
    __syncthreads();

    const float inv = 1.0f / s_norm[b];
    #pragma unroll
    for (int k = 0; k < 4; k++)
        out[(b << 6) + c4 + k] = p[k] * inv;

    if (tid == 0) g_counter = 0;       // reset for next graph replay
}

extern "C" void kernel_launch(void* const* d_in, const int* in_sizes, int n_in,
                              void* d_out, int out_size) {
    const float* x = (const float*)d_in[0];
    float* out = (float*)d_out;
    fused_pool_kernel<<<NBLK, 128>>>(x, out);
}